// round 9
// baseline (speedup 1.0000x reference)
#include <cuda_runtime.h>

// Problem constants
#define N_SONGS 100000
#define DIM     11
#define BATCH   128
#define NQUERY  20
#define NQ      (BATCH * NQUERY)   // 2560
#define H1      128
#define H2      64
#define OUTD    (NQUERY * DIM)     // 220

// Argmax kernel config
#define NB   148      // one block per SM, single wave
#define TPB  320      // 10 warps; 320 * 8 queries = 2560
#define TQ   8        // queries per thread (4 f32x2 pairs)
#define TS   256      // songs per smem tile

// Scratch (static __device__ — no allocation allowed)
__device__ float              g_produced[NQ * DIM];          // MLP output (un-normalized: argmax-invariant)
__device__ float2             g_sdup[N_SONGS * DIM];         // normalized songs, value duplicated (s,s)
__device__ unsigned long long g_best[NQ];                    // (ordered(val)<<32) | (0xFFFFFFFF - idx)

// ---------------------------------------------------------------------------
// Kernel A: encoder MLP. One block per sample, 128 threads.
// ---------------------------------------------------------------------------
__global__ void mlp_kernel(const float* __restrict__ x,
                           const float* __restrict__ W1, const float* __restrict__ b1,
                           const float* __restrict__ W2, const float* __restrict__ b2,
                           const float* __restrict__ W3, const float* __restrict__ b3) {
    __shared__ float xs[55];
    __shared__ float h1s[H1];
    __shared__ float h2s[H2];
    const int b = blockIdx.x;
    const int t = threadIdx.x;

    if (t < 55) xs[t] = x[b * 55 + t];
    __syncthreads();

    // h1 = relu(x @ W1 + b1), W1 is [55,128] row-major
    {
        float acc = b1[t];
        #pragma unroll
        for (int k = 0; k < 55; k++) acc = fmaf(xs[k], W1[k * H1 + t], acc);
        h1s[t] = fmaxf(acc, 0.0f);
    }
    __syncthreads();

    // h2 = relu(h1 @ W2 + b2), W2 is [128,64]
    if (t < H2) {
        float acc = b2[t];
        #pragma unroll 8
        for (int k = 0; k < H1; k++) acc = fmaf(h1s[k], W2[k * H2 + t], acc);
        h2s[t] = fmaxf(acc, 0.0f);
    }
    __syncthreads();

    // produced = h2 @ W3 + b3, W3 is [64,220]
    for (int j = t; j < OUTD; j += blockDim.x) {
        float acc = b3[j];
        #pragma unroll 8
        for (int k = 0; k < H2; k++) acc = fmaf(h2s[k], W3[k * OUTD + j], acc);
        g_produced[b * OUTD + j] = acc;
    }
}

// ---------------------------------------------------------------------------
// Kernel B: normalize songs, store (v,v) duplicated pairs; also init g_best.
// ---------------------------------------------------------------------------
__global__ void prep_kernel(const float* __restrict__ songs) {
    const int n = blockIdx.x * blockDim.x + threadIdx.x;
    if (n < NQ) g_best[n] = 0ull;   // smaller than any real encoded key
    if (n >= N_SONGS) return;

    float v[DIM];
    float ss = 0.0f;
    #pragma unroll
    for (int d = 0; d < DIM; d++) {
        v[d] = songs[n * DIM + d];
        ss = fmaf(v[d], v[d], ss);
    }
    // IEEE sqrt/div regardless of fast-math: keeps scale error at ~1 ulp
    const float nrm = __fsqrt_rn(ss);
    const float inv = __fdiv_rn(1.0f, fmaxf(nrm, 1e-8f));
    #pragma unroll
    for (int d = 0; d < DIM; d++) {
        const float sv = v[d] * inv;
        g_sdup[n * DIM + d] = make_float2(sv, sv);
    }
}

// ---------------------------------------------------------------------------
// Kernel C: fused dot + argmax. Each block owns a contiguous song chunk and
// scans ALL 2560 queries against it. Two queries share one f32x2 lane-pair:
//   fma.rn.f32x2( (pA[d],pB[d]), (s[d],s[d]), acc ) -> (dotA, dotB)
// 5.5 packed-FMA ops per (query,song), no horizontal reduction needed.
// ---------------------------------------------------------------------------
__global__ void __launch_bounds__(TPB, 1) argmax_kernel() {
    __shared__ float2 tile[TS * DIM];   // 22528 B

    const int t  = threadIdx.x;
    const int q0 = t * TQ;

    // Pack this thread's 8 query vectors into 4 f32x2 pair-registers per dim.
    unsigned long long pk[TQ / 2][DIM];
    #pragma unroll
    for (int pr = 0; pr < TQ / 2; pr++) {
        #pragma unroll
        for (int d = 0; d < DIM; d++) {
            const float a = g_produced[(q0 + 2 * pr + 0) * DIM + d];
            const float b = g_produced[(q0 + 2 * pr + 1) * DIM + d];
            unsigned long long p;
            asm("mov.b64 %0, {%1, %2};" : "=l"(p) : "f"(a), "f"(b));
            pk[pr][d] = p;
        }
    }

    float bv[TQ];
    int   bi[TQ];
    #pragma unroll
    for (int j = 0; j < TQ; j++) { bv[j] = -3.4e38f; bi[j] = 0; }

    const int chunk = (N_SONGS + NB - 1) / NB;           // 676
    const int n0 = blockIdx.x * chunk;
    const int n1 = min(n0 + chunk, N_SONGS);

    for (int t0 = n0; t0 < n1; t0 += TS) {
        const int tn = min(TS, n1 - t0);
        __syncthreads();
        // Stage tile (coalesced float2 copy)
        const float2* __restrict__ src = &g_sdup[(size_t)t0 * DIM];
        for (int i = t; i < tn * DIM; i += TPB) tile[i] = src[i];
        __syncthreads();

        #pragma unroll 2
        for (int s = 0; s < tn; s++) {
            // Broadcast song row (11 x LDS.64, all lanes same address)
            unsigned long long sv[DIM];
            const unsigned long long* __restrict__ srow =
                (const unsigned long long*)&tile[s * DIM];
            #pragma unroll
            for (int d = 0; d < DIM; d++) sv[d] = srow[d];

            const int n = t0 + s;
            #pragma unroll
            for (int pr = 0; pr < TQ / 2; pr++) {
                unsigned long long acc;
                asm("mul.rn.f32x2 %0, %1, %2;"
                    : "=l"(acc) : "l"(pk[pr][0]), "l"(sv[0]));
                #pragma unroll
                for (int d = 1; d < DIM; d++)
                    asm("fma.rn.f32x2 %0, %1, %2, %0;"
                        : "+l"(acc) : "l"(pk[pr][d]), "l"(sv[d]));
                float lo, hi;
                asm("mov.b64 {%0, %1}, %2;" : "=f"(lo), "=f"(hi) : "l"(acc));
                // strict > keeps the FIRST (lowest n) winner, matching jnp.argmax
                if (lo > bv[2 * pr + 0]) { bv[2 * pr + 0] = lo; bi[2 * pr + 0] = n; }
                if (hi > bv[2 * pr + 1]) { bv[2 * pr + 1] = hi; bi[2 * pr + 1] = n; }
            }
        }
    }

    // Cross-block reduction: monotone (value,index) key, first-index tie-break.
    #pragma unroll
    for (int j = 0; j < TQ; j++) {
        unsigned int ou = __float_as_uint(bv[j]);
        ou ^= ((unsigned int)((int)ou >> 31)) | 0x80000000u;   // order-preserving map
        const unsigned long long key =
            ((unsigned long long)ou << 32) |
            (unsigned long long)(0xFFFFFFFFu - (unsigned int)bi[j]);
        atomicMax(&g_best[q0 + j], key);
    }
}

// ---------------------------------------------------------------------------
// Kernel D: gather winning (un-normalized) song rows into the output.
// ---------------------------------------------------------------------------
__global__ void gather_kernel(const float* __restrict__ songs, float* __restrict__ out) {
    const int i = blockIdx.x * blockDim.x + threadIdx.x;
    if (i >= NQ * DIM) return;
    const int q = i / DIM;
    const int d = i % DIM;
    const unsigned int enc = (unsigned int)(g_best[q] & 0xFFFFFFFFull);
    const int idx = (int)(0xFFFFFFFFu - enc);
    out[i] = songs[idx * DIM + d];
}

// ---------------------------------------------------------------------------
extern "C" void kernel_launch(void* const* d_in, const int* in_sizes, int n_in,
                              void* d_out, int out_size) {
    const float* x     = (const float*)d_in[0];
    const float* W1    = (const float*)d_in[1];
    const float* b1    = (const float*)d_in[2];
    const float* W2    = (const float*)d_in[3];
    const float* b2    = (const float*)d_in[4];
    const float* W3    = (const float*)d_in[5];
    const float* b3    = (const float*)d_in[6];
    const float* songs = (const float*)d_in[7];
    float* out = (float*)d_out;

    mlp_kernel<<<BATCH, 128>>>(x, W1, b1, W2, b2, W3, b3);
    prep_kernel<<<(N_SONGS + 255) / 256, 256>>>(songs);
    argmax_kernel<<<NB, TPB>>>();
    gather_kernel<<<(NQ * DIM + 127) / 128, 128>>>(songs, out);
}